// round 2
// baseline (speedup 1.0000x reference)
#include <cuda_runtime.h>

#define NPTS 4096
#define CCH  128
#define GG   49
#define PAD  132        // smem row stride (floats)
#define MROWS 16384     // 4 levels * 4096 points

typedef unsigned long long u64t;

// packed fp32x2 FMA (SASS FFMA2) — 2 fp32 FMAs per instruction, full precision
__device__ __forceinline__ u64t ffma2(u64t a, u64t b, u64t c) {
  u64t d;
  asm("fma.rn.f32x2 %0, %1, %2, %3;" : "=l"(d) : "l"(a), "l"(b), "l"(c));
  return d;
}
__device__ __forceinline__ float p_lo(u64t v) { return __uint_as_float((unsigned)v); }
__device__ __forceinline__ float p_hi(u64t v) { return __uint_as_float((unsigned)(v >> 32)); }
__device__ __forceinline__ u64t pack2(float x, float y) {
  return ((u64t)__float_as_uint(y) << 32) | (u64t)__float_as_uint(x);
}

// ---- scratch (static device globals: allocation-free at launch time) ----
__device__ float g_fmapt[2088960];                 // fmaps transposed to [H,W,C], 4 levels
__device__ float g_X[(size_t)MROWS * 2401];        // correlation volumes (MLP1 input)
__device__ float g_H[(size_t)MROWS * 384];         // MLP1 activations

// ============================================================
// Kernel 0: transpose fmap [C,H,W] -> [H,W,C]
// ============================================================
__global__ void k_transpose(const float* __restrict__ in, int HW, int outOff) {
  int p = blockIdx.x;
  int c = threadIdx.x;
  g_fmapt[(size_t)outOff + (size_t)p * CCH + c] = in[(size_t)c * HW + p];
}

// ============================================================
// Kernel 1: per (level, point): bilinear 7x7xC gather + 49x49x128 corr GEMM
// grid = NPTS blocks, 256 threads. dyn smem = 2*GG*PAD*4 = 51744 B
// f32x2: packed along C (k-dim); acc holds (even-c, odd-c) partial sums.
// ============================================================
__global__ __launch_bounds__(256) void k_corr(
    const float* __restrict__ tfeat,   // [49, N, 128]
    const float* __restrict__ coords,  // [N, 2]
    int H, int W, int fmOff, int level, float scale)
{
  extern __shared__ float sm[];
  float* tmpl_s = sm;                // [49][PAD]
  float* cf_s   = sm + GG * PAD;     // [49][PAD]
  const float* fmap = g_fmapt + fmOff;   // [H,W,C]
  const int n = blockIdx.x;
  const int tid = threadIdx.x;

  // --- load template support features (coalesced along C) ---
  for (int idx = tid; idx < GG * CCH; idx += 256) {
    int t = idx >> 7, c = idx & 127;
    tmpl_s[t * PAD + c] = tfeat[(size_t)t * (NPTS * CCH) + (size_t)n * CCH + c];
  }

  float cx = coords[2 * n]     * scale;
  float cy = coords[2 * n + 1] * scale;

  // --- bilinear gather ---
  {
    int c    = tid & 127;
    int half = tid >> 7;
    for (int p = half; p < GG; p += 2) {
      int gi = p / 7, gj = p - gi * 7;
      float xs = cx + (float)(gi - 3);
      float ys = cy + (float)(gj - 3);
      float x0f = floorf(xs), y0f = floorf(ys);
      float wx = xs - x0f, wy = ys - y0f;
      int x0 = (int)x0f, y0 = (int)y0f;
      float w00 = (1.f - wy) * (1.f - wx);
      float w01 = (1.f - wy) * wx;
      float w10 = wy * (1.f - wx);
      float w11 = wy * wx;
      float v = 0.f;
      bool xin0 = (x0 >= 0) && (x0 < W);
      bool xin1 = (x0 + 1 >= 0) && (x0 + 1 < W);
      if (y0 >= 0 && y0 < H) {
        size_t rb = (size_t)y0 * W;
        if (xin0) v += w00 * fmap[(rb + x0) * CCH + c];
        if (xin1) v += w01 * fmap[(rb + x0 + 1) * CCH + c];
      }
      if (y0 + 1 >= 0 && y0 + 1 < H) {
        size_t rb = (size_t)(y0 + 1) * W;
        if (xin0) v += w10 * fmap[(rb + x0) * CCH + c];
        if (xin1) v += w11 * fmap[(rb + x0 + 1) * CCH + c];
      }
      cf_s[p * PAD + c] = v;
    }
  }
  __syncthreads();

  // --- 49x49 GEMM over C=128: 4x4 tile per thread, f32x2 packed over C ---
  int tx = tid & 15, ty = tid >> 4;
  u64t acc[4][4];
#pragma unroll
  for (int a = 0; a < 4; a++)
#pragma unroll
    for (int b = 0; b < 4; b++) acc[a][b] = 0ull;

  int hw[4], ij[4];
#pragma unroll
  for (int a = 0; a < 4; a++) {
    int h = ty + 16 * a; hw[a] = (h > 48) ? 48 : h;
    int j = tx + 16 * a; ij[a] = (j > 48) ? 48 : j;
  }

#pragma unroll 4
  for (int cc = 0; cc < CCH; cc += 4) {
    ulonglong2 av[4], bv[4];
#pragma unroll
    for (int a = 0; a < 4; a++) av[a] = *(const ulonglong2*)&cf_s[hw[a] * PAD + cc];
#pragma unroll
    for (int b = 0; b < 4; b++) bv[b] = *(const ulonglong2*)&tmpl_s[ij[b] * PAD + cc];
#pragma unroll
    for (int a = 0; a < 4; a++)
#pragma unroll
      for (int b = 0; b < 4; b++) {
        acc[a][b] = ffma2(av[a].x, bv[b].x, acc[a][b]);
        acc[a][b] = ffma2(av[a].y, bv[b].y, acc[a][b]);
      }
  }

  size_t rowbase = ((size_t)level * NPTS + n) * 2401;
#pragma unroll
  for (int a = 0; a < 4; a++)
#pragma unroll
    for (int b = 0; b < 4; b++)
      if ((ty + 16 * a) < GG && (tx + 16 * b) < GG)
        g_X[rowbase + (size_t)hw[a] * GG + ij[b]] = p_lo(acc[a][b]) + p_hi(acc[a][b]);
}

// ============================================================
// Kernel 2: H = gelu_exact(X @ w1 + b1)   M=16384, K=2401, N=384
// BM=128 BN=64 BK=16, 256 thr, 8x4 microtile via f32x2 packed along M.
// B stored duplicated in smem so the broadcast operand loads as (b,b) pairs.
// ============================================================
#define BM 128
#define BN 64
#define BK 16

__global__ __launch_bounds__(256) void k_mlp1(const float* __restrict__ Bw,
                                              const float* __restrict__ bias) {
  __shared__ float As[BK][BM + 4];
  __shared__ float Bs[BK][2 * BN];   // duplicated pairs
  const int K = 2401, Nn = 384;
  int tid = threadIdx.x;
  int tx = tid & 15, ty = tid >> 4;
  int col0 = blockIdx.x * BN;
  int row0 = blockIdx.y * BM;

  u64t acc[4][4];
#pragma unroll
  for (int i = 0; i < 4; i++)
#pragma unroll
    for (int j = 0; j < 4; j++) acc[i][j] = 0ull;

  for (int k0 = 0; k0 < K; k0 += BK) {
#pragma unroll
    for (int i = 0; i < 8; i++) {
      int idx = tid + i * 256;
      int m = idx >> 4, kk = idx & 15;
      int gk = k0 + kk;
      As[kk][m] = (gk < K) ? g_X[(size_t)(row0 + m) * K + gk] : 0.f;
    }
#pragma unroll
    for (int i = 0; i < 4; i++) {
      int idx = tid + i * 256;
      int kk = idx >> 6, j = idx & 63;
      int gk = k0 + kk;
      float v = (gk < K) ? Bw[(size_t)gk * Nn + col0 + j] : 0.f;
      *(u64t*)&Bs[kk][2 * j] = pack2(v, v);
    }
    __syncthreads();
#pragma unroll
    for (int kk = 0; kk < BK; kk++) {
      ulonglong2 aA = *(const ulonglong2*)&As[kk][ty * 8];      // m-pairs 0,1
      ulonglong2 aB = *(const ulonglong2*)&As[kk][ty * 8 + 4];  // m-pairs 2,3
      ulonglong2 b0 = *(const ulonglong2*)&Bs[kk][tx * 8];      // dup j0,j1
      ulonglong2 b1 = *(const ulonglong2*)&Bs[kk][tx * 8 + 4];  // dup j2,j3
      u64t a[4] = {aA.x, aA.y, aB.x, aB.y};
      u64t b[4] = {b0.x, b0.y, b1.x, b1.y};
#pragma unroll
      for (int i = 0; i < 4; i++)
#pragma unroll
        for (int j = 0; j < 4; j++) acc[i][j] = ffma2(a[i], b[j], acc[i][j]);
    }
    __syncthreads();
  }

#pragma unroll
  for (int i = 0; i < 4; i++)
#pragma unroll
    for (int j = 0; j < 4; j++) {
      int m = row0 + ty * 8 + 2 * i;
      int jg = col0 + tx * 4 + j;
      float bb = bias[jg];
      float v0 = p_lo(acc[i][j]) + bb;
      float v1 = p_hi(acc[i][j]) + bb;
      g_H[(size_t)m * 384 + jg]       = 0.5f * v0 * (1.f + erff(v0 * 0.70710678118654752f));
      g_H[(size_t)(m + 1) * 384 + jg] = 0.5f * v1 * (1.f + erff(v1 * 0.70710678118654752f));
    }
}

// ============================================================
// Kernel 3: out = H @ w2 + b2, scattered into concat layout
// M=16384, K=384, N=256. row r -> out[(r&4095)*1024 + (r>>12)*256 + j]
// ============================================================
__global__ __launch_bounds__(256) void k_mlp2(const float* __restrict__ Bw,
                                              const float* __restrict__ bias,
                                              float* __restrict__ out) {
  __shared__ float As[BK][BM + 4];
  __shared__ float Bs[BK][2 * BN];
  const int K = 384, Nn = 256;
  int tid = threadIdx.x;
  int tx = tid & 15, ty = tid >> 4;
  int col0 = blockIdx.x * BN;
  int row0 = blockIdx.y * BM;

  u64t acc[4][4];
#pragma unroll
  for (int i = 0; i < 4; i++)
#pragma unroll
    for (int j = 0; j < 4; j++) acc[i][j] = 0ull;

  for (int k0 = 0; k0 < K; k0 += BK) {
#pragma unroll
    for (int i = 0; i < 8; i++) {
      int idx = tid + i * 256;
      int m = idx >> 4, kk = idx & 15;
      As[kk][m] = g_H[(size_t)(row0 + m) * K + k0 + kk];
    }
#pragma unroll
    for (int i = 0; i < 4; i++) {
      int idx = tid + i * 256;
      int kk = idx >> 6, j = idx & 63;
      float v = Bw[(size_t)(k0 + kk) * Nn + col0 + j];
      *(u64t*)&Bs[kk][2 * j] = pack2(v, v);
    }
    __syncthreads();
#pragma unroll
    for (int kk = 0; kk < BK; kk++) {
      ulonglong2 aA = *(const ulonglong2*)&As[kk][ty * 8];
      ulonglong2 aB = *(const ulonglong2*)&As[kk][ty * 8 + 4];
      ulonglong2 b0 = *(const ulonglong2*)&Bs[kk][tx * 8];
      ulonglong2 b1 = *(const ulonglong2*)&Bs[kk][tx * 8 + 4];
      u64t a[4] = {aA.x, aA.y, aB.x, aB.y};
      u64t b[4] = {b0.x, b0.y, b1.x, b1.y};
#pragma unroll
      for (int i = 0; i < 4; i++)
#pragma unroll
        for (int j = 0; j < 4; j++) acc[i][j] = ffma2(a[i], b[j], acc[i][j]);
    }
    __syncthreads();
  }

#pragma unroll
  for (int i = 0; i < 4; i++)
#pragma unroll
    for (int j = 0; j < 4; j++) {
      int m0 = row0 + ty * 8 + 2 * i;
      int jg = col0 + tx * 4 + j;
      float bb = bias[jg];
#pragma unroll
      for (int h = 0; h < 2; h++) {
        int m = m0 + h;
        int lev = m >> 12;
        int npt = m & 4095;
        float v = (h ? p_hi(acc[i][j]) : p_lo(acc[i][j])) + bb;
        out[(size_t)npt * 1024 + lev * 256 + jg] = v;
      }
    }
}

// ============================================================
// Launch
// ============================================================
extern "C" void kernel_launch(void* const* d_in, const int* in_sizes, int n_in,
                              void* d_out, int out_size) {
  const float* fm[4] = {0, 0, 0, 0};
  const float* tf[4] = {0, 0, 0, 0};
  const float* coords = 0;
  const float* w1 = 0; const float* b1 = 0;
  const float* w2 = 0; const float* b2 = 0;
  int tfi = 0, seen98304 = 0;
  for (int i = 0; i < n_in; i++) {
    const float* p = (const float*)d_in[i];
    switch (in_sizes[i]) {
      case 1572864:  fm[0] = p; break;
      case 393216:   fm[1] = p; break;
      case 98304:    if (!seen98304) { fm[2] = p; seen98304 = 1; } else w2 = p; break;
      case 24576:    fm[3] = p; break;
      case 25690112: if (tfi < 4) tf[tfi++] = p; break;
      case 8192:     coords = p; break;
      case 921984:   w1 = p; break;
      case 384:      b1 = p; break;
      case 256:      b2 = p; break;
      default: break;
    }
  }

  static const int Hs[4]   = {96, 48, 24, 12};
  static const int Ws[4]   = {128, 64, 32, 16};
  static const int offs[4] = {0, 1572864, 1966080, 2064384};

  for (int l = 0; l < 4; l++)
    k_transpose<<<Hs[l] * Ws[l], 128>>>(fm[l], Hs[l] * Ws[l], offs[l]);

  const int corrSmem = 2 * GG * PAD * 4;  // 51744 B > 48K default
  cudaFuncSetAttribute(k_corr, cudaFuncAttributeMaxDynamicSharedMemorySize, corrSmem);
  for (int l = 0; l < 4; l++) {
    float scale = 1.f / (float)(1 << l);
    k_corr<<<NPTS, 256, corrSmem>>>(tf[l], coords, Hs[l], Ws[l], offs[l], l, scale);
  }

  k_mlp1<<<dim3(384 / BN, MROWS / BM), 256>>>(w1, b1);
  k_mlp2<<<dim3(256 / BN, MROWS / BM), 256>>>(w2, b2, (float*)d_out);
}

// round 3
// speedup vs baseline: 1.5681x; 1.5681x over previous
#include <cuda_runtime.h>

#define NPTS 4096
#define CCH  128
#define GG   49
#define PAD  132        // corr smem row stride (floats)
#define MROWS 16384     // 4 levels * 4096 points
#define XSTRIDE 2432    // padded K (76*32) for MLP1; cols [2401,2432) are zero

// ---- scratch (static device globals: allocation-free at launch time) ----
__device__ float g_fmapt[2088960];                   // fmaps transposed to [H,W,C]
__device__ float g_X[(size_t)MROWS * XSTRIDE];       // correlation volumes (padded rows)
__device__ float g_H[(size_t)MROWS * 384];           // MLP1 activations

// ---- tf32 helpers ----
__device__ __forceinline__ unsigned f2tf32(float x) {
  unsigned r; asm("cvt.rna.tf32.f32 %0, %1;" : "=r"(r) : "f"(x)); return r;
}
__device__ __forceinline__ void mma_tf32(float& d0, float& d1, float& d2, float& d3,
                                         unsigned a0, unsigned a1, unsigned a2, unsigned a3,
                                         unsigned b0, unsigned b1) {
  asm volatile("mma.sync.aligned.m16n8k8.row.col.f32.tf32.tf32.f32 "
               "{%0,%1,%2,%3}, {%4,%5,%6,%7}, {%8,%9}, {%0,%1,%2,%3};"
               : "+f"(d0), "+f"(d1), "+f"(d2), "+f"(d3)
               : "r"(a0), "r"(a1), "r"(a2), "r"(a3), "r"(b0), "r"(b1));
}

// ============================================================
// Kernel 0: transpose fmap [C,H,W] -> [H,W,C]
// ============================================================
__global__ void k_transpose(const float* __restrict__ in, int HW, int outOff) {
  int p = blockIdx.x;
  int c = threadIdx.x;
  g_fmapt[(size_t)outOff + (size_t)p * CCH + c] = in[(size_t)c * HW + p];
}

// Kernel 0b: zero the pad columns of g_X (cols 2401..2431 of every row)
__global__ void k_zeropad() {
  int i = blockIdx.x * blockDim.x + threadIdx.x;
  int row = i / 31, c = i - row * 31;
  if (row < MROWS) g_X[(size_t)row * XSTRIDE + 2401 + c] = 0.f;
}

// ============================================================
// Kernel 1: per (level, point): bilinear 7x7xC gather + 49x49x128 corr GEMM
// grid = NPTS blocks, 256 threads. dyn smem = 2*GG*PAD*4 = 51744 B
// ============================================================
__global__ __launch_bounds__(256) void k_corr(
    const float* __restrict__ tfeat,   // [49, N, 128]
    const float* __restrict__ coords,  // [N, 2]
    int H, int W, int fmOff, int level, float scale)
{
  extern __shared__ float sm[];
  float* tmpl_s = sm;                // [49][PAD]
  float* cf_s   = sm + GG * PAD;     // [49][PAD]
  const float* fmap = g_fmapt + fmOff;   // [H,W,C]
  const int n = blockIdx.x;
  const int tid = threadIdx.x;

  for (int idx = tid; idx < GG * CCH; idx += 256) {
    int t = idx >> 7, c = idx & 127;
    tmpl_s[t * PAD + c] = tfeat[(size_t)t * (NPTS * CCH) + (size_t)n * CCH + c];
  }

  float cx = coords[2 * n]     * scale;
  float cy = coords[2 * n + 1] * scale;

  {
    int c    = tid & 127;
    int half = tid >> 7;
    for (int p = half; p < GG; p += 2) {
      int gi = p / 7, gj = p - gi * 7;
      float xs = cx + (float)(gi - 3);
      float ys = cy + (float)(gj - 3);
      float x0f = floorf(xs), y0f = floorf(ys);
      float wx = xs - x0f, wy = ys - y0f;
      int x0 = (int)x0f, y0 = (int)y0f;
      float w00 = (1.f - wy) * (1.f - wx);
      float w01 = (1.f - wy) * wx;
      float w10 = wy * (1.f - wx);
      float w11 = wy * wx;
      float v = 0.f;
      bool xin0 = (x0 >= 0) && (x0 < W);
      bool xin1 = (x0 + 1 >= 0) && (x0 + 1 < W);
      if (y0 >= 0 && y0 < H) {
        size_t rb = (size_t)y0 * W;
        if (xin0) v += w00 * fmap[(rb + x0) * CCH + c];
        if (xin1) v += w01 * fmap[(rb + x0 + 1) * CCH + c];
      }
      if (y0 + 1 >= 0 && y0 + 1 < H) {
        size_t rb = (size_t)(y0 + 1) * W;
        if (xin0) v += w10 * fmap[(rb + x0) * CCH + c];
        if (xin1) v += w11 * fmap[(rb + x0 + 1) * CCH + c];
      }
      cf_s[p * PAD + c] = v;
    }
  }
  __syncthreads();

  int tx = tid & 15, ty = tid >> 4;
  float acc[4][4];
#pragma unroll
  for (int a = 0; a < 4; a++)
#pragma unroll
    for (int b = 0; b < 4; b++) acc[a][b] = 0.f;

  int hw[4], ij[4];
#pragma unroll
  for (int a = 0; a < 4; a++) {
    int h = ty + 16 * a; hw[a] = (h > 48) ? 48 : h;
    int j = tx + 16 * a; ij[a] = (j > 48) ? 48 : j;
  }

#pragma unroll 4
  for (int cc = 0; cc < CCH; cc += 4) {
    float4 av[4], bv[4];
#pragma unroll
    for (int a = 0; a < 4; a++) av[a] = *(const float4*)&cf_s[hw[a] * PAD + cc];
#pragma unroll
    for (int b = 0; b < 4; b++) bv[b] = *(const float4*)&tmpl_s[ij[b] * PAD + cc];
#pragma unroll
    for (int a = 0; a < 4; a++)
#pragma unroll
      for (int b = 0; b < 4; b++) {
        acc[a][b] += av[a].x * bv[b].x;
        acc[a][b] += av[a].y * bv[b].y;
        acc[a][b] += av[a].z * bv[b].z;
        acc[a][b] += av[a].w * bv[b].w;
      }
  }

  size_t rowbase = ((size_t)level * NPTS + n) * XSTRIDE;
#pragma unroll
  for (int a = 0; a < 4; a++)
#pragma unroll
    for (int b = 0; b < 4; b++)
      if ((ty + 16 * a) < GG && (tx + 16 * b) < GG)
        g_X[rowbase + (size_t)hw[a] * GG + ij[b]] = acc[a][b];
}

// ============================================================
// Kernel 2: H = gelu_exact(X @ w1 + b1) via 3xTF32 mma.sync
// M=16384 K=2432(padded) N=384. BM=128 BN=64 BK=32, 256 thr (8 warps),
// warp tile 32x32 (2 m-frags x 4 n-frags of m16n8k8).
// smem: Ah/Al [128][36] u32, Bh/Bl [32][72] u32  (55296 B dynamic)
// ============================================================
#define MBM 128
#define MBN 64
#define MBK 32
#define ASTR 36
#define BSTR 72

__global__ __launch_bounds__(256) void k_mlp1(const float* __restrict__ Bw,
                                              const float* __restrict__ bias) {
  extern __shared__ unsigned smu[];
  unsigned* Ah = smu;                          // [128][36]
  unsigned* Al = Ah + MBM * ASTR;              // [128][36]
  unsigned* Bh = Al + MBM * ASTR;              // [32][72]
  unsigned* Bl = Bh + MBK * BSTR;              // [32][72]

  const int K = 2401, Nn = 384;
  const int tid  = threadIdx.x;
  const int lane = tid & 31;
  const int wid  = tid >> 5;
  const int g = lane >> 2, t = lane & 3;
  const int wm = wid >> 1;                     // 0..3 -> m offset 32*wm
  const int wn = wid & 1;                      // 0..1 -> n offset 32*wn
  const int row0 = blockIdx.y * MBM;
  const int col0 = blockIdx.x * MBN;

  float acc[2][4][4];
#pragma unroll
  for (int i = 0; i < 2; i++)
#pragma unroll
    for (int j = 0; j < 4; j++)
#pragma unroll
      for (int r = 0; r < 4; r++) acc[i][j][r] = 0.f;

  for (int k0 = 0; k0 < XSTRIDE; k0 += MBK) {
    // --- load A tile: 128 rows x 32 k, float4 per thread x4 ---
#pragma unroll
    for (int i = 0; i < 4; i++) {
      int idx = tid + i * 256;          // 0..1023
      int m = idx >> 3, q = idx & 7;    // row, k-quad
      float4 v = *(const float4*)&g_X[(size_t)(row0 + m) * XSTRIDE + k0 + 4 * q];
      unsigned h0 = f2tf32(v.x), h1 = f2tf32(v.y), h2 = f2tf32(v.z), h3 = f2tf32(v.w);
      unsigned* ah = &Ah[m * ASTR + 4 * q];
      unsigned* al = &Al[m * ASTR + 4 * q];
      ah[0] = h0; ah[1] = h1; ah[2] = h2; ah[3] = h3;
      al[0] = f2tf32(v.x - __uint_as_float(h0));
      al[1] = f2tf32(v.y - __uint_as_float(h1));
      al[2] = f2tf32(v.z - __uint_as_float(h2));
      al[3] = f2tf32(v.w - __uint_as_float(h3));
    }
    // --- load B tile: 32 k-rows x 64 n, float4 per thread x2 (guard k<K) ---
#pragma unroll
    for (int i = 0; i < 2; i++) {
      int idx = tid + i * 256;          // 0..511
      int kk = idx >> 4, q = idx & 15;  // k-row, n-quad
      int gk = k0 + kk;
      float4 v = make_float4(0.f, 0.f, 0.f, 0.f);
      if (gk < K) v = *(const float4*)&Bw[(size_t)gk * Nn + col0 + 4 * q];
      unsigned h0 = f2tf32(v.x), h1 = f2tf32(v.y), h2 = f2tf32(v.z), h3 = f2tf32(v.w);
      unsigned* bh = &Bh[kk * BSTR + 4 * q];
      unsigned* bl = &Bl[kk * BSTR + 4 * q];
      bh[0] = h0; bh[1] = h1; bh[2] = h2; bh[3] = h3;
      bl[0] = f2tf32(v.x - __uint_as_float(h0));
      bl[1] = f2tf32(v.y - __uint_as_float(h1));
      bl[2] = f2tf32(v.z - __uint_as_float(h2));
      bl[3] = f2tf32(v.w - __uint_as_float(h3));
    }
    __syncthreads();

#pragma unroll
    for (int ks = 0; ks < MBK / 8; ks++) {
      int k8 = ks * 8;
      unsigned ah[2][4], al[2][4], bh[4][2], bl[4][2];
#pragma unroll
      for (int mf = 0; mf < 2; mf++) {
        int r0i = (wm * 32 + mf * 16 + g) * ASTR + k8 + t;
        int r1i = r0i + 8 * ASTR;
        ah[mf][0] = Ah[r0i];     ah[mf][1] = Ah[r1i];
        ah[mf][2] = Ah[r0i + 4]; ah[mf][3] = Ah[r1i + 4];
        al[mf][0] = Al[r0i];     al[mf][1] = Al[r1i];
        al[mf][2] = Al[r0i + 4]; al[mf][3] = Al[r1i + 4];
      }
#pragma unroll
      for (int nf = 0; nf < 4; nf++) {
        int c0i = (k8 + t) * BSTR + wn * 32 + nf * 8 + g;
        bh[nf][0] = Bh[c0i]; bh[nf][1] = Bh[c0i + 4 * BSTR];
        bl[nf][0] = Bl[c0i]; bl[nf][1] = Bl[c0i + 4 * BSTR];
      }
#pragma unroll
      for (int mf = 0; mf < 2; mf++)
#pragma unroll
        for (int nf = 0; nf < 4; nf++) {
          float* d = acc[mf][nf];
          mma_tf32(d[0], d[1], d[2], d[3],
                   ah[mf][0], ah[mf][1], ah[mf][2], ah[mf][3], bh[nf][0], bh[nf][1]);
          mma_tf32(d[0], d[1], d[2], d[3],
                   ah[mf][0], ah[mf][1], ah[mf][2], ah[mf][3], bl[nf][0], bl[nf][1]);
          mma_tf32(d[0], d[1], d[2], d[3],
                   al[mf][0], al[mf][1], al[mf][2], al[mf][3], bh[nf][0], bh[nf][1]);
        }
    }
    __syncthreads();
  }

  // --- epilogue: bias + exact GELU -> g_H ---
#pragma unroll
  for (int mf = 0; mf < 2; mf++) {
    int r0 = row0 + wm * 32 + mf * 16 + g;
#pragma unroll
    for (int nf = 0; nf < 4; nf++) {
      int c0 = col0 + wn * 32 + nf * 8 + 2 * t;
      float b0 = bias[c0], b1 = bias[c0 + 1];
      const float* d = acc[mf][nf];
      float v;
      v = d[0] + b0; g_H[(size_t)r0 * 384 + c0]           = 0.5f * v * (1.f + erff(v * 0.70710678118654752f));
      v = d[1] + b1; g_H[(size_t)r0 * 384 + c0 + 1]       = 0.5f * v * (1.f + erff(v * 0.70710678118654752f));
      v = d[2] + b0; g_H[(size_t)(r0 + 8) * 384 + c0]     = 0.5f * v * (1.f + erff(v * 0.70710678118654752f));
      v = d[3] + b1; g_H[(size_t)(r0 + 8) * 384 + c0 + 1] = 0.5f * v * (1.f + erff(v * 0.70710678118654752f));
    }
  }
}

// ============================================================
// Kernel 3: out = H @ w2 + b2, scattered into concat layout (fp32 FFMA)
// M=16384, K=384, N=256. row r -> out[(r&4095)*1024 + (r>>12)*256 + j]
// ============================================================
#define BM 128
#define BN 64
#define BK 16

__global__ __launch_bounds__(256) void k_mlp2(const float* __restrict__ Bw,
                                              const float* __restrict__ bias,
                                              float* __restrict__ out) {
  __shared__ float As[BK][BM + 4];
  __shared__ float Bs[BK][BN];
  const int K = 384, Nn = 256;
  int tid = threadIdx.x;
  int tx = tid & 15, ty = tid >> 4;
  int col0 = blockIdx.x * BN;
  int row0 = blockIdx.y * BM;

  float acc[8][4];
#pragma unroll
  for (int i = 0; i < 8; i++)
#pragma unroll
    for (int j = 0; j < 4; j++) acc[i][j] = 0.f;

  for (int k0 = 0; k0 < K; k0 += BK) {
#pragma unroll
    for (int i = 0; i < 8; i++) {
      int idx = tid + i * 256;
      int m = idx >> 4, kk = idx & 15;
      As[kk][m] = g_H[(size_t)(row0 + m) * K + k0 + kk];
    }
#pragma unroll
    for (int i = 0; i < 4; i++) {
      int idx = tid + i * 256;
      int kk = idx >> 6, j = idx & 63;
      Bs[kk][j] = Bw[(size_t)(k0 + kk) * Nn + col0 + j];
    }
    __syncthreads();
#pragma unroll
    for (int kk = 0; kk < BK; kk++) {
      float4 a0 = *(const float4*)&As[kk][ty * 8];
      float4 a1 = *(const float4*)&As[kk][ty * 8 + 4];
      float4 b0 = *(const float4*)&Bs[kk][tx * 4];
      float a[8] = {a0.x, a0.y, a0.z, a0.w, a1.x, a1.y, a1.z, a1.w};
      float b[4] = {b0.x, b0.y, b0.z, b0.w};
#pragma unroll
      for (int i = 0; i < 8; i++)
#pragma unroll
        for (int j = 0; j < 4; j++) acc[i][j] += a[i] * b[j];
    }
    __syncthreads();
  }

#pragma unroll
  for (int i = 0; i < 8; i++)
#pragma unroll
    for (int j = 0; j < 4; j++) {
      int m = row0 + ty * 8 + i;
      int lev = m >> 12;
      int npt = m & 4095;
      int jg = col0 + tx * 4 + j;
      out[(size_t)npt * 1024 + lev * 256 + jg] = acc[i][j] + bias[jg];
    }
}

// ============================================================
// Launch
// ============================================================
extern "C" void kernel_launch(void* const* d_in, const int* in_sizes, int n_in,
                              void* d_out, int out_size) {
  const float* fm[4] = {0, 0, 0, 0};
  const float* tf[4] = {0, 0, 0, 0};
  const float* coords = 0;
  const float* w1 = 0; const float* b1 = 0;
  const float* w2 = 0; const float* b2 = 0;
  int tfi = 0, seen98304 = 0;
  for (int i = 0; i < n_in; i++) {
    const float* p = (const float*)d_in[i];
    switch (in_sizes[i]) {
      case 1572864:  fm[0] = p; break;
      case 393216:   fm[1] = p; break;
      case 98304:    if (!seen98304) { fm[2] = p; seen98304 = 1; } else w2 = p; break;
      case 24576:    fm[3] = p; break;
      case 25690112: if (tfi < 4) tf[tfi++] = p; break;
      case 8192:     coords = p; break;
      case 921984:   w1 = p; break;
      case 384:      b1 = p; break;
      case 256:      b2 = p; break;
      default: break;
    }
  }

  static const int Hs[4]   = {96, 48, 24, 12};
  static const int Ws[4]   = {128, 64, 32, 16};
  static const int offs[4] = {0, 1572864, 1966080, 2064384};

  for (int l = 0; l < 4; l++)
    k_transpose<<<Hs[l] * Ws[l], 128>>>(fm[l], Hs[l] * Ws[l], offs[l]);

  k_zeropad<<<(MROWS * 31 + 255) / 256, 256>>>();

  const int corrSmem = 2 * GG * PAD * 4;  // 51744 B
  cudaFuncSetAttribute(k_corr, cudaFuncAttributeMaxDynamicSharedMemorySize, corrSmem);
  for (int l = 0; l < 4; l++) {
    float scale = 1.f / (float)(1 << l);
    k_corr<<<NPTS, 256, corrSmem>>>(tf[l], coords, Hs[l], Ws[l], offs[l], l, scale);
  }

  const int mlp1Smem = (2 * MBM * ASTR + 2 * MBK * BSTR) * 4;  // 55296 B
  cudaFuncSetAttribute(k_mlp1, cudaFuncAttributeMaxDynamicSharedMemorySize, mlp1Smem);
  k_mlp1<<<dim3(384 / MBN, MROWS / MBM), 256, mlp1Smem>>>(w1, b1);

  k_mlp2<<<dim3(256 / BN, MROWS / BM), 256>>>(w2, b2, (float*)d_out);
}